// round 11
// baseline (speedup 1.0000x reference)
#include <cuda_runtime.h>
#include <cuda_bf16.h>
#include <cuda_fp16.h>
#include <math.h>
#include <stdint.h>

// Problem constants
#define BB 2
#define SS 2048
#define DD 1024
#define HH 16
#define DH 64
#define MM (BB * SS)   // 4096 rows

// softmax scale folded into Q projection: 1/sqrt(64) * log2(e)
#define QSCALE 0.18033688011112042f

// -------------------- scratch (allocation-free rule: __device__ globals) ----
__device__ __half g_A0[MM * DD];        // attn-output / out-proj A operand
__device__ __half g_Ain0[MM * DD];      // q/k/v inputs, fp16
__device__ __half g_Ain1[MM * DD];
__device__ __half g_Ain2[MM * DD];
__device__ __half g_B0[DD * DD];        // weights transposed [N][K], fp16
__device__ __half g_B1[DD * DD];
__device__ __half g_B2[DD * DD];
__device__ __half g_B3[DD * DD];
__device__ __half g_Qf[MM * DD];        // head-split [B*H][S][DH]
__device__ __half g_Kf[MM * DD];
__device__ __half g_Vf[MM * DD];

// ============================================================================
// helpers
// ============================================================================
__device__ __forceinline__ uint32_t smem_u32(const void* p) {
    uint32_t a;
    asm("{ .reg .u64 t; cvta.to.shared.u64 t, %1; cvt.u32.u64 %0, t; }"
        : "=r"(a) : "l"(p));
    return a;
}
__device__ __forceinline__ float ex2f(float x) {
    float y;
    asm("ex2.approx.f32 %0, %1;" : "=f"(y) : "f"(x));
    return y;
}
__device__ __forceinline__ uint32_t ex2_h2(uint32_t a) {
    uint32_t d;
    asm("ex2.approx.f16x2 %0, %1;" : "=r"(d) : "r"(a));
    return d;
}

#define LDSM4(r0, r1, r2, r3, addr)                                            \
    asm volatile("ldmatrix.sync.aligned.m8n8.x4.shared.b16 {%0,%1,%2,%3}, [%4];" \
                 : "=r"(r0), "=r"(r1), "=r"(r2), "=r"(r3) : "r"(addr))
#define LDSM4T(r0, r1, r2, r3, addr)                                           \
    asm volatile("ldmatrix.sync.aligned.m8n8.x4.trans.shared.b16 {%0,%1,%2,%3}, [%4];" \
                 : "=r"(r0), "=r"(r1), "=r"(r2), "=r"(r3) : "r"(addr))

#define MMAF16(d, a, b0, b1)                                                   \
    asm volatile("mma.sync.aligned.m16n8k16.row.col.f32.f16.f16.f32 "          \
                 "{%0,%1,%2,%3}, {%4,%5,%6,%7}, {%8,%9}, {%0,%1,%2,%3};"       \
                 : "+f"((d)[0]), "+f"((d)[1]), "+f"((d)[2]), "+f"((d)[3])      \
                 : "r"((a)[0]), "r"((a)[1]), "r"((a)[2]), "r"((a)[3]),         \
                   "r"(b0), "r"(b1))

#define CP_ASYNC16(dst, src)                                                   \
    asm volatile("cp.async.cg.shared.global [%0], [%1], 16;" :: "r"(dst), "l"(src))
#define CP_COMMIT()  asm volatile("cp.async.commit_group;" ::: "memory")
#define CP_WAIT1()   asm volatile("cp.async.wait_group 1;" ::: "memory")
#define CP_WAIT0()   asm volatile("cp.async.wait_group 0;" ::: "memory")

__device__ __forceinline__ uint32_t pack_h2(float x, float y) {
    __half2 h = __floats2half2_rn(x, y);
    return *(uint32_t*)&h;
}

// ============================================================================
// conversion kernels
// ============================================================================
__global__ __launch_bounds__(256)
void conv_h3(const float4* __restrict__ q, const float4* __restrict__ k,
             const float4* __restrict__ v,
             __half* __restrict__ a0, __half* __restrict__ a1,
             __half* __restrict__ a2)
{
    const int z = blockIdx.y;
    const float4* src = (z == 0) ? q : (z == 1) ? k : v;
    __half* dst = (z == 0) ? a0 : (z == 1) ? a1 : a2;
    int i = blockIdx.x * 256 + threadIdx.x;
    float4 val = src[i];
    ((uint32_t*)dst)[i * 2 + 0] = pack_h2(val.x, val.y);
    ((uint32_t*)dst)[i * 2 + 1] = pack_h2(val.z, val.w);
}

__global__ __launch_bounds__(256)
void conv_wT4(const float* __restrict__ w0, const float* __restrict__ w1,
              const float* __restrict__ w2, const float* __restrict__ w3,
              __half* __restrict__ b0, __half* __restrict__ b1,
              __half* __restrict__ b2, __half* __restrict__ b3)
{
    const int z = blockIdx.z;
    const float* W = (z == 0) ? w0 : (z == 1) ? w1 : (z == 2) ? w2 : w3;
    __half* dst = (z == 0) ? b0 : (z == 1) ? b1 : (z == 2) ? b2 : b3;

    __shared__ float t[32][33];
    int n0 = blockIdx.x * 32, k0 = blockIdx.y * 32;
    int tx = threadIdx.x, ty = threadIdx.y;   // block (32,8)
#pragma unroll
    for (int i = 0; i < 32; i += 8)
        t[ty + i][tx] = W[(size_t)(k0 + ty + i) * DD + n0 + tx];
    __syncthreads();
#pragma unroll
    for (int i = 0; i < 32; i += 8)
        dst[(size_t)(n0 + ty + i) * DD + k0 + tx] = __float2half_rn(t[tx][ty + i]);
}

// ============================================================================
// mma.sync GEMM, single fp16 A, 3-stage cp.async ring, ONE sync per stage.
// MODE 0: fp32 natural out.  MODE 1: fp16 head-split out, scaled.
// ============================================================================
#define PADK 40
#define TILE_H (128 * PADK)
#define KSTAGES (DD / 32)
#define G_STG_H (2 * TILE_H)
#define GEMM_SMEM (3 * G_STG_H * 2)   // 61440 B

template <int MODE>
__device__ __forceinline__
void gemm_body(const __half* __restrict__ Ah, const __half* __restrict__ Bs,
               const float* __restrict__ bias, float scale,
               float* __restrict__ OutF, __half* __restrict__ O1)
{
    extern __shared__ __half smb[];
    const uint32_t sb = smem_u32(smb);
    const int t = threadIdx.x, wid = t >> 5, lane = t & 31;
    const int m0 = blockIdx.y * 128, n0 = blockIdx.x * 128;
    const int wm = (wid >> 2) * 64, wn = (wid & 3) * 32;

    const __half* srcs[2] = {Ah + (size_t)m0 * DD, Bs + (size_t)n0 * DD};

    auto issue_stage = [&](int s, int buf) {
        uint32_t base = sb + buf * G_STG_H * 2;
#pragma unroll
        for (int p = 0; p < 4; p++) {
            int j = t + p * 256;
            int tile = j >> 9;
            int c = j & 511;
            int row = c >> 2;
            int c16 = c & 3;
            const __half* g = srcs[tile] + (size_t)row * DD + s * 32 + c16 * 8;
            uint32_t d = base + (tile * TILE_H + row * PADK + c16 * 8) * 2;
            CP_ASYNC16(d, g);
        }
        CP_COMMIT();
    };

    float acc[4][4][4];
#pragma unroll
    for (int i = 0; i < 4; i++)
#pragma unroll
        for (int j = 0; j < 4; j++)
#pragma unroll
            for (int r = 0; r < 4; r++) acc[i][j][r] = 0.f;

    issue_stage(0, 0);
    issue_stage(1, 1);

    for (int s = 0; s < KSTAGES; s++) {
        CP_WAIT1();
        __syncthreads();                       // all warps done with stage s-1
        if (s + 2 < KSTAGES) issue_stage(s + 2, (s + 2) % 3);

        const uint32_t base = sb + (s % 3) * G_STG_H * 2;
#pragma unroll
        for (int kk = 0; kk < 2; kk++) {
            uint32_t ah[4][4], bf[2][4];
#pragma unroll
            for (int i = 0; i < 4; i++) {
                int row = wm + i * 16 + (lane & 15);
                int col = kk * 16 + (lane >> 4) * 8;
                uint32_t ad = base + (row * PADK + col) * 2;
                LDSM4(ah[i][0], ah[i][1], ah[i][2], ah[i][3], ad);
            }
#pragma unroll
            for (int g = 0; g < 2; g++) {
                int row = wn + g * 16 + ((lane >> 4) & 1) * 8 + (lane & 7);
                int col = kk * 16 + ((lane >> 3) & 1) * 8;
                uint32_t bd = base + (TILE_H + row * PADK + col) * 2;
                LDSM4(bf[g][0], bf[g][1], bf[g][2], bf[g][3], bd);
            }
#pragma unroll
            for (int i = 0; i < 4; i++)
#pragma unroll
                for (int j = 0; j < 4; j++) {
                    int g = j >> 1, o = (j & 1) * 2;
                    MMAF16(acc[i][j], ah[i], bf[g][o], bf[g][o + 1]);
                }
        }
    }
    CP_WAIT0();

#pragma unroll
    for (int i = 0; i < 4; i++) {
        int grow = m0 + wm + i * 16 + (lane >> 2);
#pragma unroll
        for (int j = 0; j < 4; j++) {
            int gcol = n0 + wn + j * 8 + (lane & 3) * 2;
            float bx = __ldg(&bias[gcol]), by = __ldg(&bias[gcol + 1]);
            float x0 = (acc[i][j][0] + bx) * scale, y0 = (acc[i][j][1] + by) * scale;
            float x1 = (acc[i][j][2] + bx) * scale, y1 = (acc[i][j][3] + by) * scale;
            if (MODE == 0) {
                *(float2*)&OutF[(size_t)grow * DD + gcol] = make_float2(x0, y0);
                *(float2*)&OutF[(size_t)(grow + 8) * DD + gcol] = make_float2(x1, y1);
            } else {
                int h = gcol >> 6, dh = gcol & 63;
                int b0r = grow >> 11, s0 = grow & 2047;
                size_t o0 = (((size_t)(b0r * HH + h) * SS) + s0) * DH + dh;
                int g1 = grow + 8;
                int b1r = g1 >> 11, s1 = g1 & 2047;
                size_t o1 = (((size_t)(b1r * HH + h) * SS) + s1) * DH + dh;
                *(uint32_t*)&O1[o0] = pack_h2(x0, y0);
                *(uint32_t*)&O1[o1] = pack_h2(x1, y1);
            }
        }
    }
}

struct GemmPtrs3 {
    const __half *A[3], *Bs[3];
    const float *bias[3];
    float scale[3];
    __half *O1[3];
};

__global__ __launch_bounds__(256, 2)
void gemm_mma3(GemmPtrs3 p)
{
    const int z = blockIdx.z;
    gemm_body<1>(p.A[z], p.Bs[z], p.bias[z], p.scale[z], nullptr, p.O1[z]);
}

__global__ __launch_bounds__(256, 2)
void gemm_mma1(const __half* __restrict__ Ah, const __half* __restrict__ Bs,
               const float* __restrict__ bias, float* __restrict__ OutF)
{
    gemm_body<0>(Ah, Bs, bias, 1.0f, OutF, nullptr);
}

// ============================================================================
// Flash attention, all-fp16, exp2 softmax, ones-MMA row-sum.
// NEW: 3-stage KV ring, issue-at-top, ONE __syncthreads per KV tile.
// ============================================================================
#define APAD 72
#define KV_TILE_H (64 * APAD)
#define AT_STAGE_H (2 * KV_TILE_H)
#define AT_SMEM (3 * AT_STAGE_H * 2)   // 55296 B
#define NKT (SS / 64)
#define ONES_H2 0x3C003C00u

__global__ __launch_bounds__(128, 3)
void attn_mma(const __half* __restrict__ Qf, const __half* __restrict__ Kf,
              const __half* __restrict__ Vf, __half* __restrict__ OutH)
{
    extern __shared__ __half smb[];
    const uint32_t sb = smem_u32(smb);
    const int t = threadIdx.x, wid = t >> 5, lane = t & 31;
    const int bh = blockIdx.y;
    const int q0 = blockIdx.x * 64;
    const int wm = wid * 16;
    const size_t bhoff = (size_t)bh * SS * DH;

    // ---- stage Q tile (into stage-0 buffer, consumed before KV use) ----
    {
        const __half* qs = Qf + bhoff + (size_t)q0 * DH;
#pragma unroll
        for (int p = 0; p < 4; p++) {
            int j = t + p * 128;
            int row = j >> 3;
            int c16 = j & 7;
            uint32_t d = sb + (row * APAD + c16 * 8) * 2;
            CP_ASYNC16(d, qs + (size_t)row * DH + c16 * 8);
        }
        CP_COMMIT();
        CP_WAIT0();
        __syncthreads();
    }

    uint32_t qh[4][4];
#pragma unroll
    for (int kk = 0; kk < 4; kk++) {
        int row = wm + (lane & 15);
        int col = kk * 16 + (lane >> 4) * 8;
        uint32_t ad = sb + (row * APAD + col) * 2;
        LDSM4(qh[kk][0], qh[kk][1], qh[kk][2], qh[kk][3], ad);
    }
    __syncthreads();

    const __half* kvsrc[2] = {Kf + bhoff, Vf + bhoff};
    auto issue_kv = [&](int kt, int buf) {
        uint32_t base = sb + buf * AT_STAGE_H * 2;
#pragma unroll
        for (int p = 0; p < 8; p++) {
            int j = t + p * 128;
            int tile = j >> 9;
            int row = (j >> 3) & 63;
            int c16 = j & 7;
            uint32_t d = base + (tile * KV_TILE_H + row * APAD + c16 * 8) * 2;
            CP_ASYNC16(d, kvsrc[tile] + (size_t)(kt * 64 + row) * DH + c16 * 8);
        }
        CP_COMMIT();
    };

    float o[8][4];
#pragma unroll
    for (int j = 0; j < 8; j++)
#pragma unroll
        for (int r = 0; r < 4; r++) o[j][r] = 0.f;
    float m_i[2] = {-INFINITY, -INFINITY};
    float l_i[2] = {0.f, 0.f};

    issue_kv(0, 0);
    issue_kv(1, 1);

    for (int kt = 0; kt < NKT; kt++) {
        CP_WAIT1();
        __syncthreads();                       // all warps done with tile kt-1
        if (kt + 2 < NKT) issue_kv(kt + 2, (kt + 2) % 3);

        const uint32_t base = sb + (kt % 3) * AT_STAGE_H * 2;

        // ---- scores (log2 domain) ----
        float s[8][4];
#pragma unroll
        for (int j = 0; j < 8; j++)
#pragma unroll
            for (int r = 0; r < 4; r++) s[j][r] = 0.f;

#pragma unroll
        for (int kk = 0; kk < 4; kk++) {
            uint32_t kf[4][4];
#pragma unroll
            for (int g = 0; g < 4; g++) {
                int row = g * 16 + ((lane >> 4) & 1) * 8 + (lane & 7);
                int col = kk * 16 + ((lane >> 3) & 1) * 8;
                uint32_t kd = base + (row * APAD + col) * 2;
                LDSM4(kf[g][0], kf[g][1], kf[g][2], kf[g][3], kd);
            }
#pragma unroll
            for (int j = 0; j < 8; j++) {
                int g = j >> 1, oo = (j & 1) * 2;
                MMAF16(s[j], qh[kk], kf[g][oo], kf[g][oo + 1]);
            }
        }

        // ---- online softmax, base-2, f16x2 exponent ----
        float mx[2] = {-INFINITY, -INFINITY};
#pragma unroll
        for (int j = 0; j < 8; j++) {
            mx[0] = fmaxf(mx[0], fmaxf(s[j][0], s[j][1]));
            mx[1] = fmaxf(mx[1], fmaxf(s[j][2], s[j][3]));
        }
#pragma unroll
        for (int r = 0; r < 2; r++) {
            mx[r] = fmaxf(mx[r], __shfl_xor_sync(0xffffffffu, mx[r], 1));
            mx[r] = fmaxf(mx[r], __shfl_xor_sync(0xffffffffu, mx[r], 2));
        }
        float mn[2], corr[2];
#pragma unroll
        for (int r = 0; r < 2; r++) {
            mn[r] = fmaxf(m_i[r], mx[r]);
            corr[r] = ex2f(m_i[r] - mn[r]);
            m_i[r] = mn[r];
        }
        uint32_t p2[16];
#pragma unroll
        for (int j = 0; j < 8; j++) {
            p2[j * 2 + 0] = ex2_h2(pack_h2(s[j][0] - mn[0], s[j][1] - mn[0]));
            p2[j * 2 + 1] = ex2_h2(pack_h2(s[j][2] - mn[1], s[j][3] - mn[1]));
        }
#pragma unroll
        for (int j = 0; j < 8; j++) {
            o[j][0] *= corr[0]; o[j][1] *= corr[0];
            o[j][2] *= corr[1]; o[j][3] *= corr[1];
        }

        // ---- PV + row-sum via ones-MMA ----
        float dsum[4] = {0.f, 0.f, 0.f, 0.f};
#pragma unroll
        for (int kk = 0; kk < 4; kk++) {
            uint32_t ap[4];
            ap[0] = p2[(2 * kk) * 2 + 0];
            ap[1] = p2[(2 * kk) * 2 + 1];
            ap[2] = p2[(2 * kk + 1) * 2 + 0];
            ap[3] = p2[(2 * kk + 1) * 2 + 1];

            uint32_t vf[4][4];
#pragma unroll
            for (int g = 0; g < 4; g++) {
                int row = kk * 16 + (lane & 15);
                int col = g * 16 + (lane >> 4) * 8;
                uint32_t vd = base + (KV_TILE_H + row * APAD + col) * 2;
                LDSM4T(vf[g][0], vf[g][1], vf[g][2], vf[g][3], vd);
            }
#pragma unroll
            for (int j = 0; j < 8; j++) {
                int g = j >> 1, oo = (j & 1) * 2;
                MMAF16(o[j], ap, vf[g][oo], vf[g][oo + 1]);
            }
            MMAF16(dsum, ap, ONES_H2, ONES_H2);
        }
        l_i[0] = l_i[0] * corr[0] + dsum[0];
        l_i[1] = l_i[1] * corr[1] + dsum[2];
    }

    // ---- epilogue ----
    const int b = bh >> 4, h = bh & 15;
    const float inv0 = 1.f / l_i[0], inv1 = 1.f / l_i[1];
    const int srow0 = q0 + wm + (lane >> 2);
#pragma unroll
    for (int j = 0; j < 8; j++) {
        int dh = j * 8 + (lane & 3) * 2;
        int kcol = h * 64 + dh;
        size_t o0 = ((size_t)(b * SS + srow0)) * DD + kcol;
        size_t o1 = ((size_t)(b * SS + srow0 + 8)) * DD + kcol;
        *(uint32_t*)&OutH[o0] = pack_h2(o[j][0] * inv0, o[j][1] * inv0);
        *(uint32_t*)&OutH[o1] = pack_h2(o[j][2] * inv1, o[j][3] * inv1);
    }
}

// ============================================================================
// launch
// ============================================================================
extern "C" void kernel_launch(void* const* d_in, const int* in_sizes, int n_in,
                              void* d_out, int out_size)
{
    const float* q   = (const float*)d_in[0];
    const float* k   = (const float*)d_in[1];
    const float* v   = (const float*)d_in[2];
    const float* w_q = (const float*)d_in[3];
    const float* b_q = (const float*)d_in[4];
    const float* w_k = (const float*)d_in[5];
    const float* b_k = (const float*)d_in[6];
    const float* w_v = (const float*)d_in[7];
    const float* b_v = (const float*)d_in[8];
    const float* w_o = (const float*)d_in[9];
    const float* b_o = (const float*)d_in[10];
    float* out = (float*)d_out;

    __half *pA0, *pAin0, *pAin1, *pAin2;
    __half *pB0, *pB1, *pB2, *pB3, *pQf, *pKf, *pVf;
    cudaGetSymbolAddress((void**)&pA0, g_A0);
    cudaGetSymbolAddress((void**)&pAin0, g_Ain0);
    cudaGetSymbolAddress((void**)&pAin1, g_Ain1);
    cudaGetSymbolAddress((void**)&pAin2, g_Ain2);
    cudaGetSymbolAddress((void**)&pB0, g_B0);
    cudaGetSymbolAddress((void**)&pB1, g_B1);
    cudaGetSymbolAddress((void**)&pB2, g_B2);
    cudaGetSymbolAddress((void**)&pB3, g_B3);
    cudaGetSymbolAddress((void**)&pQf, g_Qf);
    cudaGetSymbolAddress((void**)&pKf, g_Kf);
    cudaGetSymbolAddress((void**)&pVf, g_Vf);

    static int attr_set = 0;
    if (!attr_set) {
        cudaFuncSetAttribute(gemm_mma3,
                             cudaFuncAttributeMaxDynamicSharedMemorySize, GEMM_SMEM);
        cudaFuncSetAttribute(gemm_mma1,
                             cudaFuncAttributeMaxDynamicSharedMemorySize, GEMM_SMEM);
        cudaFuncSetAttribute(attn_mma,
                             cudaFuncAttributeMaxDynamicSharedMemorySize, AT_SMEM);
        attr_set = 1;
    }

    dim3 gs(MM * DD / 4 / 256, 3);
    conv_h3<<<gs, 256>>>((const float4*)q, (const float4*)k, (const float4*)v,
                         pAin0, pAin1, pAin2);
    dim3 gw(DD / 32, DD / 32, 4);
    conv_wT4<<<gw, dim3(32, 8)>>>(w_q, w_k, w_v, w_o, pB0, pB1, pB2, pB3);

    GemmPtrs3 gp;
    gp.A[0] = pAin0; gp.Bs[0] = pB0; gp.bias[0] = b_q;
    gp.scale[0] = QSCALE; gp.O1[0] = pQf;
    gp.A[1] = pAin1; gp.Bs[1] = pB1; gp.bias[1] = b_k;
    gp.scale[1] = 1.0f; gp.O1[1] = pKf;
    gp.A[2] = pAin2; gp.Bs[2] = pB2; gp.bias[2] = b_v;
    gp.scale[2] = 1.0f; gp.O1[2] = pVf;
    dim3 gg(DD / 128, MM / 128, 3);   // (8, 32, 3)
    gemm_mma3<<<gg, 256, GEMM_SMEM>>>(gp);

    dim3 ga(SS / 64, BB * HH);        // (32, 32) = 1024 CTAs
    attn_mma<<<ga, 128, AT_SMEM>>>(pQf, pKf, pVf, pA0);

    dim3 g1(DD / 128, MM / 128);
    gemm_mma1<<<g1, 256, GEMM_SMEM>>>(pA0, pB3, b_o, out);
}

// round 13
// speedup vs baseline: 1.0293x; 1.0293x over previous
#include <cuda_runtime.h>
#include <cuda_bf16.h>
#include <cuda_fp16.h>
#include <math.h>
#include <stdint.h>

// Problem constants
#define BB 2
#define SS 2048
#define DD 1024
#define HH 16
#define DH 64
#define MM (BB * SS)   // 4096 rows

// softmax scale folded into Q projection: 1/sqrt(64) * log2(e)
#define QSCALE 0.18033688011112042f

// -------------------- scratch (allocation-free rule: __device__ globals) ----
__device__ __half g_A0[MM * DD];        // attn-output / out-proj A operand
__device__ __half g_Ain0[MM * DD];      // q/k/v inputs, fp16
__device__ __half g_Ain1[MM * DD];
__device__ __half g_Ain2[MM * DD];
__device__ __half g_B0[DD * DD];        // weights transposed [N][K], fp16
__device__ __half g_B1[DD * DD];
__device__ __half g_B2[DD * DD];
__device__ __half g_B3[DD * DD];
__device__ __half g_Qf[MM * DD];        // head-split [B*H][S][DH]
__device__ __half g_Kf[MM * DD];
__device__ __half g_Vf[MM * DD];

// ============================================================================
// helpers
// ============================================================================
__device__ __forceinline__ uint32_t smem_u32(const void* p) {
    uint32_t a;
    asm("{ .reg .u64 t; cvta.to.shared.u64 t, %1; cvt.u32.u64 %0, t; }"
        : "=r"(a) : "l"(p));
    return a;
}
__device__ __forceinline__ float ex2f(float x) {
    float y;
    asm("ex2.approx.f32 %0, %1;" : "=f"(y) : "f"(x));
    return y;
}
__device__ __forceinline__ uint32_t ex2_h2(uint32_t a) {
    uint32_t d;
    asm("ex2.approx.f16x2 %0, %1;" : "=r"(d) : "r"(a));
    return d;
}

#define LDSM4(r0, r1, r2, r3, addr)                                            \
    asm volatile("ldmatrix.sync.aligned.m8n8.x4.shared.b16 {%0,%1,%2,%3}, [%4];" \
                 : "=r"(r0), "=r"(r1), "=r"(r2), "=r"(r3) : "r"(addr))
#define LDSM4T(r0, r1, r2, r3, addr)                                           \
    asm volatile("ldmatrix.sync.aligned.m8n8.x4.trans.shared.b16 {%0,%1,%2,%3}, [%4];" \
                 : "=r"(r0), "=r"(r1), "=r"(r2), "=r"(r3) : "r"(addr))

#define MMAF16(d, a, b0, b1)                                                   \
    asm volatile("mma.sync.aligned.m16n8k16.row.col.f32.f16.f16.f32 "          \
                 "{%0,%1,%2,%3}, {%4,%5,%6,%7}, {%8,%9}, {%0,%1,%2,%3};"       \
                 : "+f"((d)[0]), "+f"((d)[1]), "+f"((d)[2]), "+f"((d)[3])      \
                 : "r"((a)[0]), "r"((a)[1]), "r"((a)[2]), "r"((a)[3]),         \
                   "r"(b0), "r"(b1))

#define CP_ASYNC16(dst, src)                                                   \
    asm volatile("cp.async.cg.shared.global [%0], [%1], 16;" :: "r"(dst), "l"(src))
#define CP_COMMIT()  asm volatile("cp.async.commit_group;" ::: "memory")
#define CP_WAIT1()   asm volatile("cp.async.wait_group 1;" ::: "memory")
#define CP_WAIT0()   asm volatile("cp.async.wait_group 0;" ::: "memory")

__device__ __forceinline__ uint32_t pack_h2(float x, float y) {
    __half2 h = __floats2half2_rn(x, y);
    return *(uint32_t*)&h;
}

// ============================================================================
// conversion kernels
// ============================================================================
__global__ __launch_bounds__(256)
void conv_h3(const float4* __restrict__ q, const float4* __restrict__ k,
             const float4* __restrict__ v,
             __half* __restrict__ a0, __half* __restrict__ a1,
             __half* __restrict__ a2)
{
    const int z = blockIdx.y;
    const float4* src = (z == 0) ? q : (z == 1) ? k : v;
    __half* dst = (z == 0) ? a0 : (z == 1) ? a1 : a2;
    int i = blockIdx.x * 256 + threadIdx.x;
    float4 val = src[i];
    ((uint32_t*)dst)[i * 2 + 0] = pack_h2(val.x, val.y);
    ((uint32_t*)dst)[i * 2 + 1] = pack_h2(val.z, val.w);
}

__global__ __launch_bounds__(256)
void conv_wT4(const float* __restrict__ w0, const float* __restrict__ w1,
              const float* __restrict__ w2, const float* __restrict__ w3,
              __half* __restrict__ b0, __half* __restrict__ b1,
              __half* __restrict__ b2, __half* __restrict__ b3)
{
    const int z = blockIdx.z;
    const float* W = (z == 0) ? w0 : (z == 1) ? w1 : (z == 2) ? w2 : w3;
    __half* dst = (z == 0) ? b0 : (z == 1) ? b1 : (z == 2) ? b2 : b3;

    __shared__ float t[32][33];
    int n0 = blockIdx.x * 32, k0 = blockIdx.y * 32;
    int tx = threadIdx.x, ty = threadIdx.y;   // block (32,8)
#pragma unroll
    for (int i = 0; i < 32; i += 8)
        t[ty + i][tx] = W[(size_t)(k0 + ty + i) * DD + n0 + tx];
    __syncthreads();
#pragma unroll
    for (int i = 0; i < 32; i += 8)
        dst[(size_t)(n0 + ty + i) * DD + k0 + tx] = __float2half_rn(t[tx][ty + i]);
}

// ============================================================================
// mma.sync GEMM (R10-measured-best: 2-stage, single fp16 A).
// MODE 0: fp32 natural out.  MODE 1: fp16 head-split out, scaled.
// ============================================================================
#define PADK 40
#define TILE_H (128 * PADK)
#define KSTAGES (DD / 32)
#define G_STG_H (2 * TILE_H)
#define GEMM_SMEM (2 * G_STG_H * 2)   // 40960 B

template <int MODE>
__device__ __forceinline__
void gemm_body(const __half* __restrict__ Ah, const __half* __restrict__ Bs,
               const float* __restrict__ bias, float scale,
               float* __restrict__ OutF, __half* __restrict__ O1)
{
    extern __shared__ __half smb[];
    const uint32_t sb = smem_u32(smb);
    const int t = threadIdx.x, wid = t >> 5, lane = t & 31;
    const int m0 = blockIdx.y * 128, n0 = blockIdx.x * 128;
    const int wm = (wid >> 2) * 64, wn = (wid & 3) * 32;

    const __half* srcs[2] = {Ah + (size_t)m0 * DD, Bs + (size_t)n0 * DD};

    auto issue_stage = [&](int s, int buf) {
        uint32_t base = sb + buf * G_STG_H * 2;
#pragma unroll
        for (int p = 0; p < 4; p++) {
            int j = t + p * 256;
            int tile = j >> 9;
            int c = j & 511;
            int row = c >> 2;
            int c16 = c & 3;
            const __half* g = srcs[tile] + (size_t)row * DD + s * 32 + c16 * 8;
            uint32_t d = base + (tile * TILE_H + row * PADK + c16 * 8) * 2;
            CP_ASYNC16(d, g);
        }
        CP_COMMIT();
    };

    float acc[4][4][4];
#pragma unroll
    for (int i = 0; i < 4; i++)
#pragma unroll
        for (int j = 0; j < 4; j++)
#pragma unroll
            for (int r = 0; r < 4; r++) acc[i][j][r] = 0.f;

    issue_stage(0, 0);
    issue_stage(1, 1);

    for (int s = 0; s < KSTAGES; s++) {
        CP_WAIT1();
        __syncthreads();
        const uint32_t base = sb + (s & 1) * G_STG_H * 2;
#pragma unroll
        for (int kk = 0; kk < 2; kk++) {
            uint32_t ah[4][4], bf[2][4];
#pragma unroll
            for (int i = 0; i < 4; i++) {
                int row = wm + i * 16 + (lane & 15);
                int col = kk * 16 + (lane >> 4) * 8;
                uint32_t ad = base + (row * PADK + col) * 2;
                LDSM4(ah[i][0], ah[i][1], ah[i][2], ah[i][3], ad);
            }
#pragma unroll
            for (int g = 0; g < 2; g++) {
                int row = wn + g * 16 + ((lane >> 4) & 1) * 8 + (lane & 7);
                int col = kk * 16 + ((lane >> 3) & 1) * 8;
                uint32_t bd = base + (TILE_H + row * PADK + col) * 2;
                LDSM4(bf[g][0], bf[g][1], bf[g][2], bf[g][3], bd);
            }
#pragma unroll
            for (int i = 0; i < 4; i++)
#pragma unroll
                for (int j = 0; j < 4; j++) {
                    int g = j >> 1, o = (j & 1) * 2;
                    MMAF16(acc[i][j], ah[i], bf[g][o], bf[g][o + 1]);
                }
        }
        __syncthreads();
        if (s + 2 < KSTAGES) issue_stage(s + 2, s & 1);
    }
    CP_WAIT0();

#pragma unroll
    for (int i = 0; i < 4; i++) {
        int grow = m0 + wm + i * 16 + (lane >> 2);
#pragma unroll
        for (int j = 0; j < 4; j++) {
            int gcol = n0 + wn + j * 8 + (lane & 3) * 2;
            float bx = __ldg(&bias[gcol]), by = __ldg(&bias[gcol + 1]);
            float x0 = (acc[i][j][0] + bx) * scale, y0 = (acc[i][j][1] + by) * scale;
            float x1 = (acc[i][j][2] + bx) * scale, y1 = (acc[i][j][3] + by) * scale;
            if (MODE == 0) {
                *(float2*)&OutF[(size_t)grow * DD + gcol] = make_float2(x0, y0);
                *(float2*)&OutF[(size_t)(grow + 8) * DD + gcol] = make_float2(x1, y1);
            } else {
                int h = gcol >> 6, dh = gcol & 63;
                int b0r = grow >> 11, s0 = grow & 2047;
                size_t o0 = (((size_t)(b0r * HH + h) * SS) + s0) * DH + dh;
                int g1 = grow + 8;
                int b1r = g1 >> 11, s1 = g1 & 2047;
                size_t o1 = (((size_t)(b1r * HH + h) * SS) + s1) * DH + dh;
                *(uint32_t*)&O1[o0] = pack_h2(x0, y0);
                *(uint32_t*)&O1[o1] = pack_h2(x1, y1);
            }
        }
    }
}

struct GemmPtrs3 {
    const __half *A[3], *Bs[3];
    const float *bias[3];
    float scale[3];
    __half *O1[3];
};

__global__ __launch_bounds__(256, 2)
void gemm_mma3(GemmPtrs3 p)
{
    const int z = blockIdx.z;
    gemm_body<1>(p.A[z], p.Bs[z], p.bias[z], p.scale[z], nullptr, p.O1[z]);
}

__global__ __launch_bounds__(256, 2)
void gemm_mma1(const __half* __restrict__ Ah, const __half* __restrict__ Bs,
               const float* __restrict__ bias, float* __restrict__ OutF)
{
    gemm_body<0>(Ah, Bs, bias, 1.0f, OutF, nullptr);
}

// ============================================================================
// Flash attention (R11-measured-best: 64-row q-tile, 4 warps, 3-stage KV
// ring, one __syncthreads per tile, exp2 softmax, ones-MMA row-sum).
// ============================================================================
#define APAD 72
#define KV_TILE_H (64 * APAD)
#define AT_STAGE_H (2 * KV_TILE_H)
#define AT_SMEM (3 * AT_STAGE_H * 2)   // 55296 B
#define NKT (SS / 64)
#define ONES_H2 0x3C003C00u

__global__ __launch_bounds__(128, 3)
void attn_mma(const __half* __restrict__ Qf, const __half* __restrict__ Kf,
              const __half* __restrict__ Vf, __half* __restrict__ OutH)
{
    extern __shared__ __half smb[];
    const uint32_t sb = smem_u32(smb);
    const int t = threadIdx.x, wid = t >> 5, lane = t & 31;
    const int bh = blockIdx.y;
    const int q0 = blockIdx.x * 64;
    const int wm = wid * 16;
    const size_t bhoff = (size_t)bh * SS * DH;

    // ---- stage Q tile (into stage-0 buffer, consumed before KV use) ----
    {
        const __half* qs = Qf + bhoff + (size_t)q0 * DH;
#pragma unroll
        for (int p = 0; p < 4; p++) {
            int j = t + p * 128;
            int row = j >> 3;
            int c16 = j & 7;
            uint32_t d = sb + (row * APAD + c16 * 8) * 2;
            CP_ASYNC16(d, qs + (size_t)row * DH + c16 * 8);
        }
        CP_COMMIT();
        CP_WAIT0();
        __syncthreads();
    }

    uint32_t qh[4][4];
#pragma unroll
    for (int kk = 0; kk < 4; kk++) {
        int row = wm + (lane & 15);
        int col = kk * 16 + (lane >> 4) * 8;
        uint32_t ad = sb + (row * APAD + col) * 2;
        LDSM4(qh[kk][0], qh[kk][1], qh[kk][2], qh[kk][3], ad);
    }
    __syncthreads();

    const __half* kvsrc[2] = {Kf + bhoff, Vf + bhoff};
    auto issue_kv = [&](int kt, int buf) {
        uint32_t base = sb + buf * AT_STAGE_H * 2;
#pragma unroll
        for (int p = 0; p < 8; p++) {
            int j = t + p * 128;
            int tile = j >> 9;
            int row = (j >> 3) & 63;
            int c16 = j & 7;
            uint32_t d = base + (tile * KV_TILE_H + row * APAD + c16 * 8) * 2;
            CP_ASYNC16(d, kvsrc[tile] + (size_t)(kt * 64 + row) * DH + c16 * 8);
        }
        CP_COMMIT();
    };

    float o[8][4];
#pragma unroll
    for (int j = 0; j < 8; j++)
#pragma unroll
        for (int r = 0; r < 4; r++) o[j][r] = 0.f;
    float m_i[2] = {-INFINITY, -INFINITY};
    float l_i[2] = {0.f, 0.f};

    issue_kv(0, 0);
    issue_kv(1, 1);

    for (int kt = 0; kt < NKT; kt++) {
        CP_WAIT1();
        __syncthreads();                       // all warps done with tile kt-1
        if (kt + 2 < NKT) issue_kv(kt + 2, (kt + 2) % 3);

        const uint32_t base = sb + (kt % 3) * AT_STAGE_H * 2;

        // ---- scores (log2 domain) ----
        float s[8][4];
#pragma unroll
        for (int j = 0; j < 8; j++)
#pragma unroll
            for (int r = 0; r < 4; r++) s[j][r] = 0.f;

#pragma unroll
        for (int kk = 0; kk < 4; kk++) {
            uint32_t kf[4][4];
#pragma unroll
            for (int g = 0; g < 4; g++) {
                int row = g * 16 + ((lane >> 4) & 1) * 8 + (lane & 7);
                int col = kk * 16 + ((lane >> 3) & 1) * 8;
                uint32_t kd = base + (row * APAD + col) * 2;
                LDSM4(kf[g][0], kf[g][1], kf[g][2], kf[g][3], kd);
            }
#pragma unroll
            for (int j = 0; j < 8; j++) {
                int g = j >> 1, oo = (j & 1) * 2;
                MMAF16(s[j], qh[kk], kf[g][oo], kf[g][oo + 1]);
            }
        }

        // ---- online softmax, base-2, f16x2 exponent ----
        float mx[2] = {-INFINITY, -INFINITY};
#pragma unroll
        for (int j = 0; j < 8; j++) {
            mx[0] = fmaxf(mx[0], fmaxf(s[j][0], s[j][1]));
            mx[1] = fmaxf(mx[1], fmaxf(s[j][2], s[j][3]));
        }
#pragma unroll
        for (int r = 0; r < 2; r++) {
            mx[r] = fmaxf(mx[r], __shfl_xor_sync(0xffffffffu, mx[r], 1));
            mx[r] = fmaxf(mx[r], __shfl_xor_sync(0xffffffffu, mx[r], 2));
        }
        float mn[2], corr[2];
#pragma unroll
        for (int r = 0; r < 2; r++) {
            mn[r] = fmaxf(m_i[r], mx[r]);
            corr[r] = ex2f(m_i[r] - mn[r]);
            m_i[r] = mn[r];
        }
        uint32_t p2[16];
#pragma unroll
        for (int j = 0; j < 8; j++) {
            p2[j * 2 + 0] = ex2_h2(pack_h2(s[j][0] - mn[0], s[j][1] - mn[0]));
            p2[j * 2 + 1] = ex2_h2(pack_h2(s[j][2] - mn[1], s[j][3] - mn[1]));
        }
#pragma unroll
        for (int j = 0; j < 8; j++) {
            o[j][0] *= corr[0]; o[j][1] *= corr[0];
            o[j][2] *= corr[1]; o[j][3] *= corr[1];
        }

        // ---- PV + row-sum via ones-MMA ----
        float dsum[4] = {0.f, 0.f, 0.f, 0.f};
#pragma unroll
        for (int kk = 0; kk < 4; kk++) {
            uint32_t ap[4];
            ap[0] = p2[(2 * kk) * 2 + 0];
            ap[1] = p2[(2 * kk) * 2 + 1];
            ap[2] = p2[(2 * kk + 1) * 2 + 0];
            ap[3] = p2[(2 * kk + 1) * 2 + 1];

            uint32_t vf[4][4];
#pragma unroll
            for (int g = 0; g < 4; g++) {
                int row = kk * 16 + (lane & 15);
                int col = g * 16 + (lane >> 4) * 8;
                uint32_t vd = base + (KV_TILE_H + row * APAD + col) * 2;
                LDSM4T(vf[g][0], vf[g][1], vf[g][2], vf[g][3], vd);
            }
#pragma unroll
            for (int j = 0; j < 8; j++) {
                int g = j >> 1, oo = (j & 1) * 2;
                MMAF16(o[j], ap, vf[g][oo], vf[g][oo + 1]);
            }
            MMAF16(dsum, ap, ONES_H2, ONES_H2);
        }
        l_i[0] = l_i[0] * corr[0] + dsum[0];
        l_i[1] = l_i[1] * corr[1] + dsum[2];
    }

    // ---- epilogue ----
    const int b = bh >> 4, h = bh & 15;
    const float inv0 = 1.f / l_i[0], inv1 = 1.f / l_i[1];
    const int srow0 = q0 + wm + (lane >> 2);
#pragma unroll
    for (int j = 0; j < 8; j++) {
        int dh = j * 8 + (lane & 3) * 2;
        int kcol = h * 64 + dh;
        size_t o0 = ((size_t)(b * SS + srow0)) * DD + kcol;
        size_t o1 = ((size_t)(b * SS + srow0 + 8)) * DD + kcol;
        *(uint32_t*)&OutH[o0] = pack_h2(o[j][0] * inv0, o[j][1] * inv0);
        *(uint32_t*)&OutH[o1] = pack_h2(o[j][2] * inv1, o[j][3] * inv1);
    }
}

// ============================================================================
// launch
// ============================================================================
extern "C" void kernel_launch(void* const* d_in, const int* in_sizes, int n_in,
                              void* d_out, int out_size)
{
    const float* q   = (const float*)d_in[0];
    const float* k   = (const float*)d_in[1];
    const float* v   = (const float*)d_in[2];
    const float* w_q = (const float*)d_in[3];
    const float* b_q = (const float*)d_in[4];
    const float* w_k = (const float*)d_in[5];
    const float* b_k = (const float*)d_in[6];
    const float* w_v = (const float*)d_in[7];
    const float* b_v = (const float*)d_in[8];
    const float* w_o = (const float*)d_in[9];
    const float* b_o = (const float*)d_in[10];
    float* out = (float*)d_out;

    __half *pA0, *pAin0, *pAin1, *pAin2;
    __half *pB0, *pB1, *pB2, *pB3, *pQf, *pKf, *pVf;
    cudaGetSymbolAddress((void**)&pA0, g_A0);
    cudaGetSymbolAddress((void**)&pAin0, g_Ain0);
    cudaGetSymbolAddress((void**)&pAin1, g_Ain1);
    cudaGetSymbolAddress((void**)&pAin2, g_Ain2);
    cudaGetSymbolAddress((void**)&pB0, g_B0);
    cudaGetSymbolAddress((void**)&pB1, g_B1);
    cudaGetSymbolAddress((void**)&pB2, g_B2);
    cudaGetSymbolAddress((void**)&pB3, g_B3);
    cudaGetSymbolAddress((void**)&pQf, g_Qf);
    cudaGetSymbolAddress((void**)&pKf, g_Kf);
    cudaGetSymbolAddress((void**)&pVf, g_Vf);

    static int attr_set = 0;
    if (!attr_set) {
        cudaFuncSetAttribute(gemm_mma3,
                             cudaFuncAttributeMaxDynamicSharedMemorySize, GEMM_SMEM);
        cudaFuncSetAttribute(gemm_mma1,
                             cudaFuncAttributeMaxDynamicSharedMemorySize, GEMM_SMEM);
        cudaFuncSetAttribute(attn_mma,
                             cudaFuncAttributeMaxDynamicSharedMemorySize, AT_SMEM);
        attr_set = 1;
    }

    dim3 gs(MM * DD / 4 / 256, 3);
    conv_h3<<<gs, 256>>>((const float4*)q, (const float4*)k, (const float4*)v,
                         pAin0, pAin1, pAin2);
    dim3 gw(DD / 32, DD / 32, 4);
    conv_wT4<<<gw, dim3(32, 8)>>>(w_q, w_k, w_v, w_o, pB0, pB1, pB2, pB3);

    GemmPtrs3 gp;
    gp.A[0] = pAin0; gp.Bs[0] = pB0; gp.bias[0] = b_q;
    gp.scale[0] = QSCALE; gp.O1[0] = pQf;
    gp.A[1] = pAin1; gp.Bs[1] = pB1; gp.bias[1] = b_k;
    gp.scale[1] = 1.0f; gp.O1[1] = pKf;
    gp.A[2] = pAin2; gp.Bs[2] = pB2; gp.bias[2] = b_v;
    gp.scale[2] = 1.0f; gp.O1[2] = pVf;
    dim3 gg(DD / 128, MM / 128, 3);   // (8, 32, 3)
    gemm_mma3<<<gg, 256, GEMM_SMEM>>>(gp);

    dim3 ga(SS / 64, BB * HH);        // (32, 32) = 1024 CTAs
    attn_mma<<<ga, 128, AT_SMEM>>>(pQf, pKf, pVf, pA0);

    dim3 g1(DD / 128, MM / 128);
    gemm_mma1<<<g1, 256, GEMM_SMEM>>>(pA0, pB3, b_o, out);
}

// round 14
// speedup vs baseline: 1.0729x; 1.0424x over previous
#include <cuda_runtime.h>
#include <cuda_bf16.h>
#include <cuda_fp16.h>
#include <math.h>
#include <stdint.h>

// Problem constants
#define BB 2
#define SS 2048
#define DD 1024
#define HH 16
#define DH 64
#define MM (BB * SS)   // 4096 rows

// softmax scale folded into Q projection: 1/sqrt(64) * log2(e)
#define QSCALE 0.18033688011112042f

// -------------------- scratch (allocation-free rule: __device__ globals) ----
__device__ __half g_A0[MM * DD];        // attn-output / out-proj A operand
__device__ __half g_Ain0[MM * DD];      // q/k/v inputs, fp16
__device__ __half g_Ain1[MM * DD];
__device__ __half g_Ain2[MM * DD];
__device__ __half g_B0[DD * DD];        // weights transposed [N][K], fp16
__device__ __half g_B1[DD * DD];
__device__ __half g_B2[DD * DD];
__device__ __half g_B3[DD * DD];
__device__ __half g_Qf[MM * DD];        // head-split [B*H][S][DH]
__device__ __half g_Kf[MM * DD];
__device__ __half g_Vf[MM * DD];

// ============================================================================
// helpers
// ============================================================================
__device__ __forceinline__ uint32_t smem_u32(const void* p) {
    uint32_t a;
    asm("{ .reg .u64 t; cvta.to.shared.u64 t, %1; cvt.u32.u64 %0, t; }"
        : "=r"(a) : "l"(p));
    return a;
}
__device__ __forceinline__ float ex2f(float x) {
    float y;
    asm("ex2.approx.f32 %0, %1;" : "=f"(y) : "f"(x));
    return y;
}
__device__ __forceinline__ uint32_t ex2_h2(uint32_t a) {
    uint32_t d;
    asm("ex2.approx.f16x2 %0, %1;" : "=r"(d) : "r"(a));
    return d;
}

#define LDSM4(r0, r1, r2, r3, addr)                                            \
    asm volatile("ldmatrix.sync.aligned.m8n8.x4.shared.b16 {%0,%1,%2,%3}, [%4];" \
                 : "=r"(r0), "=r"(r1), "=r"(r2), "=r"(r3) : "r"(addr))
#define LDSM4T(r0, r1, r2, r3, addr)                                           \
    asm volatile("ldmatrix.sync.aligned.m8n8.x4.trans.shared.b16 {%0,%1,%2,%3}, [%4];" \
                 : "=r"(r0), "=r"(r1), "=r"(r2), "=r"(r3) : "r"(addr))

#define MMAF16(d, a, b0, b1)                                                   \
    asm volatile("mma.sync.aligned.m16n8k16.row.col.f32.f16.f16.f32 "          \
                 "{%0,%1,%2,%3}, {%4,%5,%6,%7}, {%8,%9}, {%0,%1,%2,%3};"       \
                 : "+f"((d)[0]), "+f"((d)[1]), "+f"((d)[2]), "+f"((d)[3])      \
                 : "r"((a)[0]), "r"((a)[1]), "r"((a)[2]), "r"((a)[3]),         \
                   "r"(b0), "r"(b1))

#define CP_ASYNC16(dst, src)                                                   \
    asm volatile("cp.async.cg.shared.global [%0], [%1], 16;" :: "r"(dst), "l"(src))
#define CP_COMMIT()  asm volatile("cp.async.commit_group;" ::: "memory")
#define CP_WAIT1()   asm volatile("cp.async.wait_group 1;" ::: "memory")
#define CP_WAIT0()   asm volatile("cp.async.wait_group 0;" ::: "memory")

__device__ __forceinline__ uint32_t pack_h2(float x, float y) {
    __half2 h = __floats2half2_rn(x, y);
    return *(uint32_t*)&h;
}

// ============================================================================
// conversion kernels
// ============================================================================
__global__ __launch_bounds__(256)
void conv_h3(const float4* __restrict__ q, const float4* __restrict__ k,
             const float4* __restrict__ v,
             __half* __restrict__ a0, __half* __restrict__ a1,
             __half* __restrict__ a2)
{
    const int z = blockIdx.y;
    const float4* src = (z == 0) ? q : (z == 1) ? k : v;
    __half* dst = (z == 0) ? a0 : (z == 1) ? a1 : a2;
    int i = blockIdx.x * 256 + threadIdx.x;
    float4 val = src[i];
    ((uint32_t*)dst)[i * 2 + 0] = pack_h2(val.x, val.y);
    ((uint32_t*)dst)[i * 2 + 1] = pack_h2(val.z, val.w);
}

__global__ __launch_bounds__(256)
void conv_wT4(const float* __restrict__ w0, const float* __restrict__ w1,
              const float* __restrict__ w2, const float* __restrict__ w3,
              __half* __restrict__ b0, __half* __restrict__ b1,
              __half* __restrict__ b2, __half* __restrict__ b3)
{
    const int z = blockIdx.z;
    const float* W = (z == 0) ? w0 : (z == 1) ? w1 : (z == 2) ? w2 : w3;
    __half* dst = (z == 0) ? b0 : (z == 1) ? b1 : (z == 2) ? b2 : b3;

    __shared__ float t[32][33];
    int n0 = blockIdx.x * 32, k0 = blockIdx.y * 32;
    int tx = threadIdx.x, ty = threadIdx.y;   // block (32,8)
#pragma unroll
    for (int i = 0; i < 32; i += 8)
        t[ty + i][tx] = W[(size_t)(k0 + ty + i) * DD + n0 + tx];
    __syncthreads();
#pragma unroll
    for (int i = 0; i < 32; i += 8)
        dst[(size_t)(n0 + ty + i) * DD + k0 + tx] = __float2half_rn(t[tx][ty + i]);
}

// ============================================================================
// mma.sync GEMM — R14: 64x64 warp tile, 4 warps (128 thr), 128x128 CTA tile.
// Per kk-slice: 8 LDSM4 feed 32 MMAs (ratio 4).  Same k-accumulation order
// as R13 (stage-ascending, kk-ascending) -> bit-identical numerics.
// MODE 0: fp32 natural out.  MODE 1: fp16 head-split out, scaled.
// ============================================================================
#define PADK 40
#define TILE_H (128 * PADK)
#define KSTAGES (DD / 32)
#define G_STG_H (2 * TILE_H)
#define GEMM_SMEM (2 * G_STG_H * 2)   // 40960 B

template <int MODE>
__device__ __forceinline__
void gemm_body(const __half* __restrict__ Ah, const __half* __restrict__ Bs,
               const float* __restrict__ bias, float scale,
               float* __restrict__ OutF, __half* __restrict__ O1)
{
    extern __shared__ __half smb[];
    const uint32_t sb = smem_u32(smb);
    const int t = threadIdx.x, wid = t >> 5, lane = t & 31;
    const int m0 = blockIdx.y * 128, n0 = blockIdx.x * 128;
    const int wm = (wid >> 1) * 64, wn = (wid & 1) * 64;

    const __half* srcs[2] = {Ah + (size_t)m0 * DD, Bs + (size_t)n0 * DD};

    auto issue_stage = [&](int s, int buf) {
        uint32_t base = sb + buf * G_STG_H * 2;
#pragma unroll
        for (int p = 0; p < 8; p++) {
            int j = t + p * 128;              // 0..1023 16B chunks
            int tile = j >> 9;
            int c = j & 511;
            int row = c >> 2;
            int c16 = c & 3;
            const __half* g = srcs[tile] + (size_t)row * DD + s * 32 + c16 * 8;
            uint32_t d = base + (tile * TILE_H + row * PADK + c16 * 8) * 2;
            CP_ASYNC16(d, g);
        }
        CP_COMMIT();
    };

    float acc[4][8][4];
#pragma unroll
    for (int i = 0; i < 4; i++)
#pragma unroll
        for (int j = 0; j < 8; j++)
#pragma unroll
            for (int r = 0; r < 4; r++) acc[i][j][r] = 0.f;

    issue_stage(0, 0);
    issue_stage(1, 1);

    for (int s = 0; s < KSTAGES; s++) {
        CP_WAIT1();
        __syncthreads();
        const uint32_t base = sb + (s & 1) * G_STG_H * 2;
#pragma unroll
        for (int kk = 0; kk < 2; kk++) {
            uint32_t ah[4][4], bf[4][4];
#pragma unroll
            for (int i = 0; i < 4; i++) {
                int row = wm + i * 16 + (lane & 15);
                int col = kk * 16 + (lane >> 4) * 8;
                uint32_t ad = base + (row * PADK + col) * 2;
                LDSM4(ah[i][0], ah[i][1], ah[i][2], ah[i][3], ad);
            }
#pragma unroll
            for (int g = 0; g < 4; g++) {
                int row = wn + g * 16 + ((lane >> 4) & 1) * 8 + (lane & 7);
                int col = kk * 16 + ((lane >> 3) & 1) * 8;
                uint32_t bd = base + (TILE_H + row * PADK + col) * 2;
                LDSM4(bf[g][0], bf[g][1], bf[g][2], bf[g][3], bd);
            }
#pragma unroll
            for (int i = 0; i < 4; i++)
#pragma unroll
                for (int j = 0; j < 8; j++) {
                    int g = j >> 1, o = (j & 1) * 2;
                    MMAF16(acc[i][j], ah[i], bf[g][o], bf[g][o + 1]);
                }
        }
        __syncthreads();
        if (s + 2 < KSTAGES) issue_stage(s + 2, s & 1);
    }
    CP_WAIT0();

#pragma unroll
    for (int i = 0; i < 4; i++) {
        int grow = m0 + wm + i * 16 + (lane >> 2);
#pragma unroll
        for (int j = 0; j < 8; j++) {
            int gcol = n0 + wn + j * 8 + (lane & 3) * 2;
            float bx = __ldg(&bias[gcol]), by = __ldg(&bias[gcol + 1]);
            float x0 = (acc[i][j][0] + bx) * scale, y0 = (acc[i][j][1] + by) * scale;
            float x1 = (acc[i][j][2] + bx) * scale, y1 = (acc[i][j][3] + by) * scale;
            if (MODE == 0) {
                *(float2*)&OutF[(size_t)grow * DD + gcol] = make_float2(x0, y0);
                *(float2*)&OutF[(size_t)(grow + 8) * DD + gcol] = make_float2(x1, y1);
            } else {
                int h = gcol >> 6, dh = gcol & 63;
                int b0r = grow >> 11, s0 = grow & 2047;
                size_t o0 = (((size_t)(b0r * HH + h) * SS) + s0) * DH + dh;
                int g1 = grow + 8;
                int b1r = g1 >> 11, s1 = g1 & 2047;
                size_t o1 = (((size_t)(b1r * HH + h) * SS) + s1) * DH + dh;
                *(uint32_t*)&O1[o0] = pack_h2(x0, y0);
                *(uint32_t*)&O1[o1] = pack_h2(x1, y1);
            }
        }
    }
}

struct GemmPtrs3 {
    const __half *A[3], *Bs[3];
    const float *bias[3];
    float scale[3];
    __half *O1[3];
};

__global__ __launch_bounds__(128, 2)
void gemm_mma3(GemmPtrs3 p)
{
    const int z = blockIdx.z;
    gemm_body<1>(p.A[z], p.Bs[z], p.bias[z], p.scale[z], nullptr, p.O1[z]);
}

__global__ __launch_bounds__(128, 2)
void gemm_mma1(const __half* __restrict__ Ah, const __half* __restrict__ Bs,
               const float* __restrict__ bias, float* __restrict__ OutF)
{
    gemm_body<0>(Ah, Bs, bias, 1.0f, OutF, nullptr);
}

// ============================================================================
// Flash attention (R13-proven, unchanged: 64-row q-tile, 4 warps, 3-stage
// KV ring, one __syncthreads per tile, exp2 softmax, ones-MMA row-sum).
// ============================================================================
#define APAD 72
#define KV_TILE_H (64 * APAD)
#define AT_STAGE_H (2 * KV_TILE_H)
#define AT_SMEM (3 * AT_STAGE_H * 2)   // 55296 B
#define NKT (SS / 64)
#define ONES_H2 0x3C003C00u

__global__ __launch_bounds__(128, 3)
void attn_mma(const __half* __restrict__ Qf, const __half* __restrict__ Kf,
              const __half* __restrict__ Vf, __half* __restrict__ OutH)
{
    extern __shared__ __half smb[];
    const uint32_t sb = smem_u32(smb);
    const int t = threadIdx.x, wid = t >> 5, lane = t & 31;
    const int bh = blockIdx.y;
    const int q0 = blockIdx.x * 64;
    const int wm = wid * 16;
    const size_t bhoff = (size_t)bh * SS * DH;

    // ---- stage Q tile ----
    {
        const __half* qs = Qf + bhoff + (size_t)q0 * DH;
#pragma unroll
        for (int p = 0; p < 4; p++) {
            int j = t + p * 128;
            int row = j >> 3;
            int c16 = j & 7;
            uint32_t d = sb + (row * APAD + c16 * 8) * 2;
            CP_ASYNC16(d, qs + (size_t)row * DH + c16 * 8);
        }
        CP_COMMIT();
        CP_WAIT0();
        __syncthreads();
    }

    uint32_t qh[4][4];
#pragma unroll
    for (int kk = 0; kk < 4; kk++) {
        int row = wm + (lane & 15);
        int col = kk * 16 + (lane >> 4) * 8;
        uint32_t ad = sb + (row * APAD + col) * 2;
        LDSM4(qh[kk][0], qh[kk][1], qh[kk][2], qh[kk][3], ad);
    }
    __syncthreads();

    const __half* kvsrc[2] = {Kf + bhoff, Vf + bhoff};
    auto issue_kv = [&](int kt, int buf) {
        uint32_t base = sb + buf * AT_STAGE_H * 2;
#pragma unroll
        for (int p = 0; p < 8; p++) {
            int j = t + p * 128;
            int tile = j >> 9;
            int row = (j >> 3) & 63;
            int c16 = j & 7;
            uint32_t d = base + (tile * KV_TILE_H + row * APAD + c16 * 8) * 2;
            CP_ASYNC16(d, kvsrc[tile] + (size_t)(kt * 64 + row) * DH + c16 * 8);
        }
        CP_COMMIT();
    };

    float o[8][4];
#pragma unroll
    for (int j = 0; j < 8; j++)
#pragma unroll
        for (int r = 0; r < 4; r++) o[j][r] = 0.f;
    float m_i[2] = {-INFINITY, -INFINITY};
    float l_i[2] = {0.f, 0.f};

    issue_kv(0, 0);
    issue_kv(1, 1);

    for (int kt = 0; kt < NKT; kt++) {
        CP_WAIT1();
        __syncthreads();
        if (kt + 2 < NKT) issue_kv(kt + 2, (kt + 2) % 3);

        const uint32_t base = sb + (kt % 3) * AT_STAGE_H * 2;

        float s[8][4];
#pragma unroll
        for (int j = 0; j < 8; j++)
#pragma unroll
            for (int r = 0; r < 4; r++) s[j][r] = 0.f;

#pragma unroll
        for (int kk = 0; kk < 4; kk++) {
            uint32_t kf[4][4];
#pragma unroll
            for (int g = 0; g < 4; g++) {
                int row = g * 16 + ((lane >> 4) & 1) * 8 + (lane & 7);
                int col = kk * 16 + ((lane >> 3) & 1) * 8;
                uint32_t kd = base + (row * APAD + col) * 2;
                LDSM4(kf[g][0], kf[g][1], kf[g][2], kf[g][3], kd);
            }
#pragma unroll
            for (int j = 0; j < 8; j++) {
                int g = j >> 1, oo = (j & 1) * 2;
                MMAF16(s[j], qh[kk], kf[g][oo], kf[g][oo + 1]);
            }
        }

        float mx[2] = {-INFINITY, -INFINITY};
#pragma unroll
        for (int j = 0; j < 8; j++) {
            mx[0] = fmaxf(mx[0], fmaxf(s[j][0], s[j][1]));
            mx[1] = fmaxf(mx[1], fmaxf(s[j][2], s[j][3]));
        }
#pragma unroll
        for (int r = 0; r < 2; r++) {
            mx[r] = fmaxf(mx[r], __shfl_xor_sync(0xffffffffu, mx[r], 1));
            mx[r] = fmaxf(mx[r], __shfl_xor_sync(0xffffffffu, mx[r], 2));
        }
        float mn[2], corr[2];
#pragma unroll
        for (int r = 0; r < 2; r++) {
            mn[r] = fmaxf(m_i[r], mx[r]);
            corr[r] = ex2f(m_i[r] - mn[r]);
            m_i[r] = mn[r];
        }
        uint32_t p2[16];
#pragma unroll
        for (int j = 0; j < 8; j++) {
            p2[j * 2 + 0] = ex2_h2(pack_h2(s[j][0] - mn[0], s[j][1] - mn[0]));
            p2[j * 2 + 1] = ex2_h2(pack_h2(s[j][2] - mn[1], s[j][3] - mn[1]));
        }
#pragma unroll
        for (int j = 0; j < 8; j++) {
            o[j][0] *= corr[0]; o[j][1] *= corr[0];
            o[j][2] *= corr[1]; o[j][3] *= corr[1];
        }

        float dsum[4] = {0.f, 0.f, 0.f, 0.f};
#pragma unroll
        for (int kk = 0; kk < 4; kk++) {
            uint32_t ap[4];
            ap[0] = p2[(2 * kk) * 2 + 0];
            ap[1] = p2[(2 * kk) * 2 + 1];
            ap[2] = p2[(2 * kk + 1) * 2 + 0];
            ap[3] = p2[(2 * kk + 1) * 2 + 1];

            uint32_t vf[4][4];
#pragma unroll
            for (int g = 0; g < 4; g++) {
                int row = kk * 16 + (lane & 15);
                int col = g * 16 + (lane >> 4) * 8;
                uint32_t vd = base + (KV_TILE_H + row * APAD + col) * 2;
                LDSM4T(vf[g][0], vf[g][1], vf[g][2], vf[g][3], vd);
            }
#pragma unroll
            for (int j = 0; j < 8; j++) {
                int g = j >> 1, oo = (j & 1) * 2;
                MMAF16(o[j], ap, vf[g][oo], vf[g][oo + 1]);
            }
            MMAF16(dsum, ap, ONES_H2, ONES_H2);
        }
        l_i[0] = l_i[0] * corr[0] + dsum[0];
        l_i[1] = l_i[1] * corr[1] + dsum[2];
    }

    const int b = bh >> 4, h = bh & 15;
    const float inv0 = 1.f / l_i[0], inv1 = 1.f / l_i[1];
    const int srow0 = q0 + wm + (lane >> 2);
#pragma unroll
    for (int j = 0; j < 8; j++) {
        int dh = j * 8 + (lane & 3) * 2;
        int kcol = h * 64 + dh;
        size_t o0 = ((size_t)(b * SS + srow0)) * DD + kcol;
        size_t o1 = ((size_t)(b * SS + srow0 + 8)) * DD + kcol;
        *(uint32_t*)&OutH[o0] = pack_h2(o[j][0] * inv0, o[j][1] * inv0);
        *(uint32_t*)&OutH[o1] = pack_h2(o[j][2] * inv1, o[j][3] * inv1);
    }
}

// ============================================================================
// launch
// ============================================================================
extern "C" void kernel_launch(void* const* d_in, const int* in_sizes, int n_in,
                              void* d_out, int out_size)
{
    const float* q   = (const float*)d_in[0];
    const float* k   = (const float*)d_in[1];
    const float* v   = (const float*)d_in[2];
    const float* w_q = (const float*)d_in[3];
    const float* b_q = (const float*)d_in[4];
    const float* w_k = (const float*)d_in[5];
    const float* b_k = (const float*)d_in[6];
    const float* w_v = (const float*)d_in[7];
    const float* b_v = (const float*)d_in[8];
    const float* w_o = (const float*)d_in[9];
    const float* b_o = (const float*)d_in[10];
    float* out = (float*)d_out;

    __half *pA0, *pAin0, *pAin1, *pAin2;
    __half *pB0, *pB1, *pB2, *pB3, *pQf, *pKf, *pVf;
    cudaGetSymbolAddress((void**)&pA0, g_A0);
    cudaGetSymbolAddress((void**)&pAin0, g_Ain0);
    cudaGetSymbolAddress((void**)&pAin1, g_Ain1);
    cudaGetSymbolAddress((void**)&pAin2, g_Ain2);
    cudaGetSymbolAddress((void**)&pB0, g_B0);
    cudaGetSymbolAddress((void**)&pB1, g_B1);
    cudaGetSymbolAddress((void**)&pB2, g_B2);
    cudaGetSymbolAddress((void**)&pB3, g_B3);
    cudaGetSymbolAddress((void**)&pQf, g_Qf);
    cudaGetSymbolAddress((void**)&pKf, g_Kf);
    cudaGetSymbolAddress((void**)&pVf, g_Vf);

    static int attr_set = 0;
    if (!attr_set) {
        cudaFuncSetAttribute(gemm_mma3,
                             cudaFuncAttributeMaxDynamicSharedMemorySize, GEMM_SMEM);
        cudaFuncSetAttribute(gemm_mma1,
                             cudaFuncAttributeMaxDynamicSharedMemorySize, GEMM_SMEM);
        cudaFuncSetAttribute(attn_mma,
                             cudaFuncAttributeMaxDynamicSharedMemorySize, AT_SMEM);
        attr_set = 1;
    }

    dim3 gs(MM * DD / 4 / 256, 3);
    conv_h3<<<gs, 256>>>((const float4*)q, (const float4*)k, (const float4*)v,
                         pAin0, pAin1, pAin2);
    dim3 gw(DD / 32, DD / 32, 4);
    conv_wT4<<<gw, dim3(32, 8)>>>(w_q, w_k, w_v, w_o, pB0, pB1, pB2, pB3);

    GemmPtrs3 gp;
    gp.A[0] = pAin0; gp.Bs[0] = pB0; gp.bias[0] = b_q;
    gp.scale[0] = QSCALE; gp.O1[0] = pQf;
    gp.A[1] = pAin1; gp.Bs[1] = pB1; gp.bias[1] = b_k;
    gp.scale[1] = 1.0f; gp.O1[1] = pKf;
    gp.A[2] = pAin2; gp.Bs[2] = pB2; gp.bias[2] = b_v;
    gp.scale[2] = 1.0f; gp.O1[2] = pVf;
    dim3 gg(DD / 128, MM / 128, 3);   // (8, 32, 3)
    gemm_mma3<<<gg, 128, GEMM_SMEM>>>(gp);

    dim3 ga(SS / 64, BB * HH);        // (32, 32) = 1024 CTAs
    attn_mma<<<ga, 128, AT_SMEM>>>(pQf, pKf, pVf, pA0);

    dim3 g1(DD / 128, MM / 128);
    gemm_mma1<<<g1, 128, GEMM_SMEM>>>(pA0, pB3, b_o, out);
}

// round 15
// speedup vs baseline: 1.0970x; 1.0224x over previous
#include <cuda_runtime.h>
#include <cuda_bf16.h>
#include <cuda_fp16.h>
#include <math.h>
#include <stdint.h>

// Problem constants
#define BB 2
#define SS 2048
#define DD 1024
#define HH 16
#define DH 64
#define MM (BB * SS)   // 4096 rows

// softmax scale folded into Q projection: 1/sqrt(64) * log2(e)
#define QSCALE 0.18033688011112042f

// -------------------- scratch (allocation-free rule: __device__ globals) ----
__device__ __half g_A0[MM * DD];        // attn-output / out-proj A operand
__device__ __half g_Ain0[MM * DD];      // q/k/v inputs, fp16
__device__ __half g_Ain1[MM * DD];
__device__ __half g_Ain2[MM * DD];
__device__ __half g_B0[DD * DD];        // weights transposed [N][K], fp16
__device__ __half g_B1[DD * DD];
__device__ __half g_B2[DD * DD];
__device__ __half g_B3[DD * DD];
__device__ __half g_Qf[MM * DD];        // head-split [B*H][S][DH]
__device__ __half g_Kf[MM * DD];
__device__ __half g_Vf[MM * DD];

// ============================================================================
// helpers
// ============================================================================
__device__ __forceinline__ uint32_t smem_u32(const void* p) {
    uint32_t a;
    asm("{ .reg .u64 t; cvta.to.shared.u64 t, %1; cvt.u32.u64 %0, t; }"
        : "=r"(a) : "l"(p));
    return a;
}
__device__ __forceinline__ float ex2f(float x) {
    float y;
    asm("ex2.approx.f32 %0, %1;" : "=f"(y) : "f"(x));
    return y;
}
__device__ __forceinline__ uint32_t ex2_h2(uint32_t a) {
    uint32_t d;
    asm("ex2.approx.f16x2 %0, %1;" : "=r"(d) : "r"(a));
    return d;
}

#define LDSM4(r0, r1, r2, r3, addr)                                            \
    asm volatile("ldmatrix.sync.aligned.m8n8.x4.shared.b16 {%0,%1,%2,%3}, [%4];" \
                 : "=r"(r0), "=r"(r1), "=r"(r2), "=r"(r3) : "r"(addr))
#define LDSM4T(r0, r1, r2, r3, addr)                                           \
    asm volatile("ldmatrix.sync.aligned.m8n8.x4.trans.shared.b16 {%0,%1,%2,%3}, [%4];" \
                 : "=r"(r0), "=r"(r1), "=r"(r2), "=r"(r3) : "r"(addr))

#define MMAF16(d, a, b0, b1)                                                   \
    asm volatile("mma.sync.aligned.m16n8k16.row.col.f32.f16.f16.f32 "          \
                 "{%0,%1,%2,%3}, {%4,%5,%6,%7}, {%8,%9}, {%0,%1,%2,%3};"       \
                 : "+f"((d)[0]), "+f"((d)[1]), "+f"((d)[2]), "+f"((d)[3])      \
                 : "r"((a)[0]), "r"((a)[1]), "r"((a)[2]), "r"((a)[3]),         \
                   "r"(b0), "r"(b1))

#define CP_ASYNC16(dst, src)                                                   \
    asm volatile("cp.async.cg.shared.global [%0], [%1], 16;" :: "r"(dst), "l"(src))
#define CP_COMMIT()  asm volatile("cp.async.commit_group;" ::: "memory")
#define CP_WAIT1()   asm volatile("cp.async.wait_group 1;" ::: "memory")
#define CP_WAIT0()   asm volatile("cp.async.wait_group 0;" ::: "memory")

__device__ __forceinline__ uint32_t pack_h2(float x, float y) {
    __half2 h = __floats2half2_rn(x, y);
    return *(uint32_t*)&h;
}

// ============================================================================
// conversion kernels
// ============================================================================
__global__ __launch_bounds__(256)
void conv_h3(const float4* __restrict__ q, const float4* __restrict__ k,
             const float4* __restrict__ v,
             __half* __restrict__ a0, __half* __restrict__ a1,
             __half* __restrict__ a2)
{
    const int z = blockIdx.y;
    const float4* src = (z == 0) ? q : (z == 1) ? k : v;
    __half* dst = (z == 0) ? a0 : (z == 1) ? a1 : a2;
    int i = blockIdx.x * 256 + threadIdx.x;
    float4 val = src[i];
    ((uint32_t*)dst)[i * 2 + 0] = pack_h2(val.x, val.y);
    ((uint32_t*)dst)[i * 2 + 1] = pack_h2(val.z, val.w);
}

__global__ __launch_bounds__(256)
void conv_wT4(const float* __restrict__ w0, const float* __restrict__ w1,
              const float* __restrict__ w2, const float* __restrict__ w3,
              __half* __restrict__ b0, __half* __restrict__ b1,
              __half* __restrict__ b2, __half* __restrict__ b3)
{
    const int z = blockIdx.z;
    const float* W = (z == 0) ? w0 : (z == 1) ? w1 : (z == 2) ? w2 : w3;
    __half* dst = (z == 0) ? b0 : (z == 1) ? b1 : (z == 2) ? b2 : b3;

    __shared__ float t[32][33];
    int n0 = blockIdx.x * 32, k0 = blockIdx.y * 32;
    int tx = threadIdx.x, ty = threadIdx.y;   // block (32,8)
#pragma unroll
    for (int i = 0; i < 32; i += 8)
        t[ty + i][tx] = W[(size_t)(k0 + ty + i) * DD + n0 + tx];
    __syncthreads();
#pragma unroll
    for (int i = 0; i < 32; i += 8)
        dst[(size_t)(n0 + ty + i) * DD + k0 + tx] = __float2half_rn(t[tx][ty + i]);
}

// ============================================================================
// mma.sync GEMM (R14-proven: 64x64 warp tile, 4 warps, 2-stage).
// MODE 0: fp32 natural out.  MODE 1: fp16 head-split out, scaled.
// ============================================================================
#define PADK 40
#define TILE_H (128 * PADK)
#define KSTAGES (DD / 32)
#define G_STG_H (2 * TILE_H)
#define GEMM_SMEM (2 * G_STG_H * 2)   // 40960 B

template <int MODE>
__device__ __forceinline__
void gemm_body(const __half* __restrict__ Ah, const __half* __restrict__ Bs,
               const float* __restrict__ bias, float scale,
               float* __restrict__ OutF, __half* __restrict__ O1)
{
    extern __shared__ __half smb[];
    const uint32_t sb = smem_u32(smb);
    const int t = threadIdx.x, wid = t >> 5, lane = t & 31;
    const int m0 = blockIdx.y * 128, n0 = blockIdx.x * 128;
    const int wm = (wid >> 1) * 64, wn = (wid & 1) * 64;

    const __half* srcs[2] = {Ah + (size_t)m0 * DD, Bs + (size_t)n0 * DD};

    auto issue_stage = [&](int s, int buf) {
        uint32_t base = sb + buf * G_STG_H * 2;
#pragma unroll
        for (int p = 0; p < 8; p++) {
            int j = t + p * 128;
            int tile = j >> 9;
            int c = j & 511;
            int row = c >> 2;
            int c16 = c & 3;
            const __half* g = srcs[tile] + (size_t)row * DD + s * 32 + c16 * 8;
            uint32_t d = base + (tile * TILE_H + row * PADK + c16 * 8) * 2;
            CP_ASYNC16(d, g);
        }
        CP_COMMIT();
    };

    float acc[4][8][4];
#pragma unroll
    for (int i = 0; i < 4; i++)
#pragma unroll
        for (int j = 0; j < 8; j++)
#pragma unroll
            for (int r = 0; r < 4; r++) acc[i][j][r] = 0.f;

    issue_stage(0, 0);
    issue_stage(1, 1);

    for (int s = 0; s < KSTAGES; s++) {
        CP_WAIT1();
        __syncthreads();
        const uint32_t base = sb + (s & 1) * G_STG_H * 2;
#pragma unroll
        for (int kk = 0; kk < 2; kk++) {
            uint32_t ah[4][4], bf[4][4];
#pragma unroll
            for (int i = 0; i < 4; i++) {
                int row = wm + i * 16 + (lane & 15);
                int col = kk * 16 + (lane >> 4) * 8;
                uint32_t ad = base + (row * PADK + col) * 2;
                LDSM4(ah[i][0], ah[i][1], ah[i][2], ah[i][3], ad);
            }
#pragma unroll
            for (int g = 0; g < 4; g++) {
                int row = wn + g * 16 + ((lane >> 4) & 1) * 8 + (lane & 7);
                int col = kk * 16 + ((lane >> 3) & 1) * 8;
                uint32_t bd = base + (TILE_H + row * PADK + col) * 2;
                LDSM4(bf[g][0], bf[g][1], bf[g][2], bf[g][3], bd);
            }
#pragma unroll
            for (int i = 0; i < 4; i++)
#pragma unroll
                for (int j = 0; j < 8; j++) {
                    int g = j >> 1, o = (j & 1) * 2;
                    MMAF16(acc[i][j], ah[i], bf[g][o], bf[g][o + 1]);
                }
        }
        __syncthreads();
        if (s + 2 < KSTAGES) issue_stage(s + 2, s & 1);
    }
    CP_WAIT0();

#pragma unroll
    for (int i = 0; i < 4; i++) {
        int grow = m0 + wm + i * 16 + (lane >> 2);
#pragma unroll
        for (int j = 0; j < 8; j++) {
            int gcol = n0 + wn + j * 8 + (lane & 3) * 2;
            float bx = __ldg(&bias[gcol]), by = __ldg(&bias[gcol + 1]);
            float x0 = (acc[i][j][0] + bx) * scale, y0 = (acc[i][j][1] + by) * scale;
            float x1 = (acc[i][j][2] + bx) * scale, y1 = (acc[i][j][3] + by) * scale;
            if (MODE == 0) {
                *(float2*)&OutF[(size_t)grow * DD + gcol] = make_float2(x0, y0);
                *(float2*)&OutF[(size_t)(grow + 8) * DD + gcol] = make_float2(x1, y1);
            } else {
                int h = gcol >> 6, dh = gcol & 63;
                int b0r = grow >> 11, s0 = grow & 2047;
                size_t o0 = (((size_t)(b0r * HH + h) * SS) + s0) * DH + dh;
                int g1 = grow + 8;
                int b1r = g1 >> 11, s1 = g1 & 2047;
                size_t o1 = (((size_t)(b1r * HH + h) * SS) + s1) * DH + dh;
                *(uint32_t*)&O1[o0] = pack_h2(x0, y0);
                *(uint32_t*)&O1[o1] = pack_h2(x1, y1);
            }
        }
    }
}

struct GemmPtrs3 {
    const __half *A[3], *Bs[3];
    const float *bias[3];
    float scale[3];
    __half *O1[3];
};

__global__ __launch_bounds__(128, 2)
void gemm_mma3(GemmPtrs3 p)
{
    const int z = blockIdx.z;
    gemm_body<1>(p.A[z], p.Bs[z], p.bias[z], p.scale[z], nullptr, p.O1[z]);
}

__global__ __launch_bounds__(128, 2)
void gemm_mma1(const __half* __restrict__ Ah, const __half* __restrict__ Bs,
               const float* __restrict__ bias, float* __restrict__ OutF)
{
    gemm_body<0>(Ah, Bs, bias, 1.0f, OutF, nullptr);
}

// ============================================================================
// Flash attention — R15: same arithmetic as R13/R14, but 2-stage KV ring
// (R10-proven dual-sync skeleton) + __launch_bounds__(128,4) for 4 CTAs/SM.
// smem/CTA = 36864 B -> 4 x 36.9 KB = 147 KB/SM.
// ============================================================================
#define APAD 72
#define KV_TILE_H (64 * APAD)
#define AT_STAGE_H (2 * KV_TILE_H)
#define AT_SMEM (2 * AT_STAGE_H * 2)   // 36864 B
#define NKT (SS / 64)
#define ONES_H2 0x3C003C00u

__global__ __launch_bounds__(128, 4)
void attn_mma(const __half* __restrict__ Qf, const __half* __restrict__ Kf,
              const __half* __restrict__ Vf, __half* __restrict__ OutH)
{
    extern __shared__ __half smb[];
    const uint32_t sb = smem_u32(smb);
    const int t = threadIdx.x, wid = t >> 5, lane = t & 31;
    const int bh = blockIdx.y;
    const int q0 = blockIdx.x * 64;
    const int wm = wid * 16;
    const size_t bhoff = (size_t)bh * SS * DH;

    // ---- stage Q tile ----
    {
        const __half* qs = Qf + bhoff + (size_t)q0 * DH;
#pragma unroll
        for (int p = 0; p < 4; p++) {
            int j = t + p * 128;
            int row = j >> 3;
            int c16 = j & 7;
            uint32_t d = sb + (row * APAD + c16 * 8) * 2;
            CP_ASYNC16(d, qs + (size_t)row * DH + c16 * 8);
        }
        CP_COMMIT();
        CP_WAIT0();
        __syncthreads();
    }

    uint32_t qh[4][4];
#pragma unroll
    for (int kk = 0; kk < 4; kk++) {
        int row = wm + (lane & 15);
        int col = kk * 16 + (lane >> 4) * 8;
        uint32_t ad = sb + (row * APAD + col) * 2;
        LDSM4(qh[kk][0], qh[kk][1], qh[kk][2], qh[kk][3], ad);
    }
    __syncthreads();

    const __half* kvsrc[2] = {Kf + bhoff, Vf + bhoff};
    auto issue_kv = [&](int kt, int buf) {
        uint32_t base = sb + buf * AT_STAGE_H * 2;
#pragma unroll
        for (int p = 0; p < 8; p++) {
            int j = t + p * 128;
            int tile = j >> 9;
            int row = (j >> 3) & 63;
            int c16 = j & 7;
            uint32_t d = base + (tile * KV_TILE_H + row * APAD + c16 * 8) * 2;
            CP_ASYNC16(d, kvsrc[tile] + (size_t)(kt * 64 + row) * DH + c16 * 8);
        }
        CP_COMMIT();
    };

    float o[8][4];
#pragma unroll
    for (int j = 0; j < 8; j++)
#pragma unroll
        for (int r = 0; r < 4; r++) o[j][r] = 0.f;
    float m_i[2] = {-INFINITY, -INFINITY};
    float l_i[2] = {0.f, 0.f};

    issue_kv(0, 0);
    issue_kv(1, 1);

    for (int kt = 0; kt < NKT; kt++) {
        CP_WAIT1();
        __syncthreads();
        const uint32_t base = sb + (kt & 1) * AT_STAGE_H * 2;

        // ---- scores (log2 domain) ----
        float s[8][4];
#pragma unroll
        for (int j = 0; j < 8; j++)
#pragma unroll
            for (int r = 0; r < 4; r++) s[j][r] = 0.f;

#pragma unroll
        for (int kk = 0; kk < 4; kk++) {
            uint32_t kf[4][4];
#pragma unroll
            for (int g = 0; g < 4; g++) {
                int row = g * 16 + ((lane >> 4) & 1) * 8 + (lane & 7);
                int col = kk * 16 + ((lane >> 3) & 1) * 8;
                uint32_t kd = base + (row * APAD + col) * 2;
                LDSM4(kf[g][0], kf[g][1], kf[g][2], kf[g][3], kd);
            }
#pragma unroll
            for (int j = 0; j < 8; j++) {
                int g = j >> 1, oo = (j & 1) * 2;
                MMAF16(s[j], qh[kk], kf[g][oo], kf[g][oo + 1]);
            }
        }

        // ---- online softmax, base-2, f16x2 exponent ----
        float mx[2] = {-INFINITY, -INFINITY};
#pragma unroll
        for (int j = 0; j < 8; j++) {
            mx[0] = fmaxf(mx[0], fmaxf(s[j][0], s[j][1]));
            mx[1] = fmaxf(mx[1], fmaxf(s[j][2], s[j][3]));
        }
#pragma unroll
        for (int r = 0; r < 2; r++) {
            mx[r] = fmaxf(mx[r], __shfl_xor_sync(0xffffffffu, mx[r], 1));
            mx[r] = fmaxf(mx[r], __shfl_xor_sync(0xffffffffu, mx[r], 2));
        }
        float mn[2], corr[2];
#pragma unroll
        for (int r = 0; r < 2; r++) {
            mn[r] = fmaxf(m_i[r], mx[r]);
            corr[r] = ex2f(m_i[r] - mn[r]);
            m_i[r] = mn[r];
        }
        uint32_t p2[16];
#pragma unroll
        for (int j = 0; j < 8; j++) {
            p2[j * 2 + 0] = ex2_h2(pack_h2(s[j][0] - mn[0], s[j][1] - mn[0]));
            p2[j * 2 + 1] = ex2_h2(pack_h2(s[j][2] - mn[1], s[j][3] - mn[1]));
        }
#pragma unroll
        for (int j = 0; j < 8; j++) {
            o[j][0] *= corr[0]; o[j][1] *= corr[0];
            o[j][2] *= corr[1]; o[j][3] *= corr[1];
        }

        // ---- PV + row-sum via ones-MMA ----
        float dsum[4] = {0.f, 0.f, 0.f, 0.f};
#pragma unroll
        for (int kk = 0; kk < 4; kk++) {
            uint32_t ap[4];
            ap[0] = p2[(2 * kk) * 2 + 0];
            ap[1] = p2[(2 * kk) * 2 + 1];
            ap[2] = p2[(2 * kk + 1) * 2 + 0];
            ap[3] = p2[(2 * kk + 1) * 2 + 1];

            uint32_t vf[4][4];
#pragma unroll
            for (int g = 0; g < 4; g++) {
                int row = kk * 16 + (lane & 15);
                int col = g * 16 + (lane >> 4) * 8;
                uint32_t vd = base + (KV_TILE_H + row * APAD + col) * 2;
                LDSM4T(vf[g][0], vf[g][1], vf[g][2], vf[g][3], vd);
            }
#pragma unroll
            for (int j = 0; j < 8; j++) {
                int g = j >> 1, oo = (j & 1) * 2;
                MMAF16(o[j], ap, vf[g][oo], vf[g][oo + 1]);
            }
            MMAF16(dsum, ap, ONES_H2, ONES_H2);
        }
        l_i[0] = l_i[0] * corr[0] + dsum[0];
        l_i[1] = l_i[1] * corr[1] + dsum[2];

        __syncthreads();                       // all warps done with buffer kt&1
        if (kt + 2 < NKT) issue_kv(kt + 2, kt & 1);
    }

    // ---- epilogue ----
    const int b = bh >> 4, h = bh & 15;
    const float inv0 = 1.f / l_i[0], inv1 = 1.f / l_i[1];
    const int srow0 = q0 + wm + (lane >> 2);
#pragma unroll
    for (int j = 0; j < 8; j++) {
        int dh = j * 8 + (lane & 3) * 2;
        int kcol = h * 64 + dh;
        size_t o0 = ((size_t)(b * SS + srow0)) * DD + kcol;
        size_t o1 = ((size_t)(b * SS + srow0 + 8)) * DD + kcol;
        *(uint32_t*)&OutH[o0] = pack_h2(o[j][0] * inv0, o[j][1] * inv0);
        *(uint32_t*)&OutH[o1] = pack_h2(o[j][2] * inv1, o[j][3] * inv1);
    }
}

// ============================================================================
// launch
// ============================================================================
extern "C" void kernel_launch(void* const* d_in, const int* in_sizes, int n_in,
                              void* d_out, int out_size)
{
    const float* q   = (const float*)d_in[0];
    const float* k   = (const float*)d_in[1];
    const float* v   = (const float*)d_in[2];
    const float* w_q = (const float*)d_in[3];
    const float* b_q = (const float*)d_in[4];
    const float* w_k = (const float*)d_in[5];
    const float* b_k = (const float*)d_in[6];
    const float* w_v = (const float*)d_in[7];
    const float* b_v = (const float*)d_in[8];
    const float* w_o = (const float*)d_in[9];
    const float* b_o = (const float*)d_in[10];
    float* out = (float*)d_out;

    __half *pA0, *pAin0, *pAin1, *pAin2;
    __half *pB0, *pB1, *pB2, *pB3, *pQf, *pKf, *pVf;
    cudaGetSymbolAddress((void**)&pA0, g_A0);
    cudaGetSymbolAddress((void**)&pAin0, g_Ain0);
    cudaGetSymbolAddress((void**)&pAin1, g_Ain1);
    cudaGetSymbolAddress((void**)&pAin2, g_Ain2);
    cudaGetSymbolAddress((void**)&pB0, g_B0);
    cudaGetSymbolAddress((void**)&pB1, g_B1);
    cudaGetSymbolAddress((void**)&pB2, g_B2);
    cudaGetSymbolAddress((void**)&pB3, g_B3);
    cudaGetSymbolAddress((void**)&pQf, g_Qf);
    cudaGetSymbolAddress((void**)&pKf, g_Kf);
    cudaGetSymbolAddress((void**)&pVf, g_Vf);

    static int attr_set = 0;
    if (!attr_set) {
        cudaFuncSetAttribute(gemm_mma3,
                             cudaFuncAttributeMaxDynamicSharedMemorySize, GEMM_SMEM);
        cudaFuncSetAttribute(gemm_mma1,
                             cudaFuncAttributeMaxDynamicSharedMemorySize, GEMM_SMEM);
        cudaFuncSetAttribute(attn_mma,
                             cudaFuncAttributeMaxDynamicSharedMemorySize, AT_SMEM);
        attr_set = 1;
    }

    dim3 gs(MM * DD / 4 / 256, 3);
    conv_h3<<<gs, 256>>>((const float4*)q, (const float4*)k, (const float4*)v,
                         pAin0, pAin1, pAin2);
    dim3 gw(DD / 32, DD / 32, 4);
    conv_wT4<<<gw, dim3(32, 8)>>>(w_q, w_k, w_v, w_o, pB0, pB1, pB2, pB3);

    GemmPtrs3 gp;
    gp.A[0] = pAin0; gp.Bs[0] = pB0; gp.bias[0] = b_q;
    gp.scale[0] = QSCALE; gp.O1[0] = pQf;
    gp.A[1] = pAin1; gp.Bs[1] = pB1; gp.bias[1] = b_k;
    gp.scale[1] = 1.0f; gp.O1[1] = pKf;
    gp.A[2] = pAin2; gp.Bs[2] = pB2; gp.bias[2] = b_v;
    gp.scale[2] = 1.0f; gp.O1[2] = pVf;
    dim3 gg(DD / 128, MM / 128, 3);   // (8, 32, 3)
    gemm_mma3<<<gg, 128, GEMM_SMEM>>>(gp);

    dim3 ga(SS / 64, BB * HH);        // (32, 32) = 1024 CTAs
    attn_mma<<<ga, 128, AT_SMEM>>>(pQf, pKf, pVf, pA0);

    dim3 g1(DD / 128, MM / 128);
    gemm_mma1<<<g1, 128, GEMM_SMEM>>>(pA0, pB3, b_o, out);
}